// round 15
// baseline (speedup 1.0000x reference)
#include <cuda_runtime.h>
#include <math.h>

// Problem shapes (fixed): x (4,1,512,180) float32 -> out (4,1,512,512) float32
#define NB   4
#define H    512
#define WIN  180
#define L    180
#define W    512

// Padded pair table: index k = (b+1) + PAD, zeros outside valid core.
// Entries pre-rescaled: (P[b] - b*dP, dP) so sample = q.x + iy*q.y (iy global).
#define PAD      112
#define PSTRIDE2 744

__device__ static __align__(16) float2 g_pairs[NB * L * PSTRIDE2];

// Per-(tile, angle) metadata: (cA, cB, as_float(ws), as_float(cnt16 | flag<<16))
//   J-major (lanes sweep j): cA = ca,  cB = -sa, flag = 0
//   I-major (lanes sweep i): cA = -sa, cB = ca,  flag = 1  (chosen when |sa|<|ca|)
#define TJ   32
#define TI   32
#define NTX  (W / TJ)      // 16
#define NTY  (W / TI)      // 16
#define NMETA (NTX * NTY * L)
__device__ static float4 g_tmeta[NMETA];

// ---------------------------------------------------------------------------
// Fused prep + meta.
// ---------------------------------------------------------------------------
#define PREP_BLOCKS (NB * L)
#define META_BLOCKS ((NMETA + 511) / 512)

__global__ void __launch_bounds__(512) irad_prep_meta(const float* __restrict__ x) {
    __shared__ float col[H];
    const int bx  = blockIdx.x;
    const int tid = threadIdx.x;

    if (bx < PREP_BLOCKS) {
        const int l = bx % L;
        const int n = bx / L;

        float Xc  = fmaf((float)l, 2.0f / 179.0f, -1.0f);
        float ix  = (Xc + 1.0f) * 0.5f * 179.0f;
        float i0f = floorf(ix);
        float wx1 = ix - i0f;
        float wx0 = 1.0f - wx1;
        int   i0  = (int)i0f;
        int   i1  = i0 + 1;
        bool  v0  = (i0 >= 0) && (i0 <= WIN - 1);
        bool  v1  = (i1 >= 0) && (i1 <= WIN - 1);

        const float* xn = x + (size_t)n * H * WIN;
        {
            const int r = tid;                       // 512 threads = H rows
            float a = v0 ? xn[r * WIN + i0] : 0.0f;
            float b = v1 ? xn[r * WIN + i1] : 0.0f;
            col[r] = wx0 * a + wx1 * b;
        }
        __syncthreads();

        float2* pr = g_pairs + (size_t)(n * L + l) * PSTRIDE2;
        for (int k = tid; k < PSTRIDE2; k += 512) {
            int kk = k - PAD;                                    // = b+1
            float P  = (kk >= 1 && kk <= 512) ? col[kk - 1] : 0.0f;
            float Pn = (kk >= 0 && kk <= 511) ? col[kk]     : 0.0f;
            float d  = Pn - P;
            pr[k] = make_float2(fmaf(-(float)(kk - 1), d, P), d);
        }
    } else {
        int idx = (bx - PREP_BLOCKS) * 512 + tid;
        if (idx >= NMETA) return;
        int l    = idx % L;
        int tile = idx / L;
        int j0   = (tile % NTX) * TJ;
        int i0t  = (tile / NTX) * TI;

        float rad = (float)l * (3.14159265358979323846f / 180.0f);
        float ca  = cosf(rad) * 255.5f;
        float sa  = sinf(rad) * 255.5f;

        float uj0 = fmaf((float)j0,           2.0f / 511.0f, -1.0f);
        float uj1 = fmaf((float)(j0 + TJ-1),  2.0f / 511.0f, -1.0f);
        float vi0 = fmaf((float)i0t,          2.0f / 511.0f, -1.0f);
        float vi1 = fmaf((float)(i0t + TI-1), 2.0f / 511.0f, -1.0f);

        float jlo = fminf(ca * uj0, ca * uj1);
        float jhi = fmaxf(ca * uj0, ca * uj1);
        float ilo = fminf(sa * vi0, sa * vi1);
        float ihi = fmaxf(sa * vi0, sa * vi1);
        float iymin = 255.5f + jlo - ihi;
        float iymax = 255.5f + jhi - ilo;

        int ws  = (int)floorf(iymin) - 1;           // extra guard entry
        ws &= ~1;                                   // even for 16B alignment
        int cnt = (int)floorf(iymax) + 3 - ws;      // guard above too
        int cnt16 = (cnt + 1) >> 1;                 // <= 26 16B chunks

        int iMaj = (fabsf(sa) < fabsf(ca)) ? 1 : 0; // lane axis = smaller coeff
        float cA = iMaj ? -sa : ca;
        float cB = iMaj ? ca  : -sa;

        g_tmeta[idx] = make_float4(cA, cB, __int_as_float(ws),
                                   __int_as_float(cnt16 | (iMaj << 16)));
    }
}

// ---------------------------------------------------------------------------
// Main: 32x32 tile, 256 threads, 4 px/thread. Per-angle lane-axis selection:
// J-angles: lanes sweep j -> accA (pixel i=i0t+wid+8k, j=j0+lane).
// I-angles: lanes sweep i -> accB (pixel i=i0t+lane, j=j0+wid+8k).
// Final smem transpose merges accB into the output.
// ---------------------------------------------------------------------------
#define CH   36     // angles per chunk (180 = 5*36)
#define NCH  (L / CH)
#define WMAX 52     // entries per angle window (incl. guards), 16B-aligned

__device__ __forceinline__ void cp_async16(unsigned dst, const void* src) {
    asm volatile("cp.async.cg.shared.global [%0], [%1], 16;\n"
                 :: "r"(dst), "l"(src));
}
__device__ __forceinline__ void cp_async_commit() {
    asm volatile("cp.async.commit_group;\n");
}
__device__ __forceinline__ void cp_async_wait_all() {
    asm volatile("cp.async.wait_group 0;\n");
}

__global__ void __launch_bounds__(256) irad_main(float* __restrict__ out) {
    __shared__ float2 sP[2 * CH * WMAX];
    __shared__ float4 sMeta[2 * CH];   // (cA, cB, as_float(byte base), flag)
    __shared__ float  sT[TI][TJ + 1];  // transpose buffer for accB

    const int n    = blockIdx.z;
    const int j0   = blockIdx.x * TJ;
    const int i0t  = blockIdx.y * TI;
    const int t    = threadIdx.x;
    const int lane = t & 31;
    const int wid  = t >> 5;           // 0..7
    const int j    = j0 + lane;

    const float uj  = fmaf((float)j, 2.0f / 511.0f, -1.0f);            // u(j0+lane)
    const float uLi = fmaf((float)(i0t + lane), 2.0f / 511.0f, -1.0f); // u(i0t+lane)
    const float duJ = (float)(j0 - i0t) * (2.0f / 511.0f);             // u(j0+m)-u(i0t+m)

    float ui[4], accA[4], accB[4];
#pragma unroll
    for (int k = 0; k < 4; k++) {
        ui[k]   = fmaf((float)(i0t + wid + 8 * k), 2.0f / 511.0f, -1.0f);
        accA[k] = 0.0f;
        accB[k] = 0.0f;
    }

    const float2* gp = g_pairs + (size_t)n * L * PSTRIDE2;
    const float4* tm = g_tmeta + (size_t)(blockIdx.y * NTX + blockIdx.x) * L;
    const char* sPc = (const char*)sP;
    const unsigned sPb = (unsigned)__cvta_generic_to_shared(sP);

    // ---- stage(chunk c into buffer b): LDG.128 meta + 1 cp.async/lane ----
    auto stage = [&](int c, int b) {
        const int c0 = c * CH;
        const int bofs = b * CH;
        for (int lc = wid; lc < CH; lc += 8) {
            const float4 m = tm[c0 + lc];
            const int ws    = __float_as_int(m.z);
            const int packed = __float_as_int(m.w);
            const int cnt16 = packed & 0xFFFF;

            const float2* src = gp + (size_t)(c0 + lc) * PSTRIDE2 + (ws + PAD);
            unsigned dst = sPb + (unsigned)((bofs + lc) * WMAX) * 8u;
            if (lane < cnt16)
                cp_async16(dst + (unsigned)lane * 16u, src + 2 * lane);
            if (lane == 0) {
                // slot for floor e is (e - ws + 1): table entry b lives at b+1
                int ab8 = (((bofs + lc) * WMAX) + 1 - ws) * 8;
                sMeta[bofs + lc] = make_float4(m.x, m.y, __int_as_float(ab8),
                                               __int_as_float(packed >> 16));
            }
        }
        cp_async_commit();
    };

    stage(0, 0);

    for (int c = 0; c < NCH; c++) {
        const int b = c & 1;
        cp_async_wait_all();
        __syncthreads();                       // buf b ready; buf b^1 free

        if (c + 1 < NCH) stage(c + 1, b ^ 1);  // issue-only prefetch

        const float4* mp = sMeta + b * CH;
        for (int lc = 0; lc < CH; lc++) {
            const float4 m  = mp[lc];
            const char* pb  = sPc + __float_as_int(m.z);
            if (__float_as_int(m.w) == 0) {
                // J-major: t0 from lane j-coord; k-term -sa on u(i0t+wid+8k)
                const float t0 = fmaf(m.x, uj, 255.5f);
#pragma unroll
                for (int k = 0; k < 4; k++) {
                    float iy = fmaf(m.y, ui[k], t0);
                    int   e  = __float2int_rd(iy);
                    float2 q = *(const float2*)(pb + ((unsigned)e << 3));
                    accA[k] = fmaf(iy, q.y, accA[k] + q.x);
                }
            } else {
                // I-major: t0 from lane i-coord + folded tile offset;
                // k-term ca on u(j0+wid+8k) = ui[k] + duJ (folded into t0)
                const float t0 = fmaf(m.y, duJ, fmaf(m.x, uLi, 255.5f));
#pragma unroll
                for (int k = 0; k < 4; k++) {
                    float iy = fmaf(m.y, ui[k], t0);
                    int   e  = __float2int_rd(iy);
                    float2 q = *(const float2*)(pb + ((unsigned)e << 3));
                    accB[k] = fmaf(iy, q.y, accB[k] + q.x);
                }
            }
        }
    }

    // ---- merge: accB holds pixel (i=i0t+lane, j=j0+wid+8k); transpose ----
    __syncthreads();
#pragma unroll
    for (int k = 0; k < 4; k++)
        sT[lane][wid + 8 * k] = accB[k];
    __syncthreads();

    const float scale = (float)(M_PI / 360.0);   // pi / (2*L)
    float* po = out + ((size_t)(n * W + i0t + wid) * W) + j;
#pragma unroll
    for (int k = 0; k < 4; k++) {
        float v = accA[k] + sT[wid + 8 * k][lane];
        po[(size_t)(8 * k) * W] = v * scale;
    }
}

// ---------------------------------------------------------------------------
extern "C" void kernel_launch(void* const* d_in, const int* in_sizes, int n_in,
                              void* d_out, int out_size) {
    const float* x = (const float*)d_in[0];
    float* out = (float*)d_out;
    (void)in_sizes; (void)n_in; (void)out_size;

    irad_prep_meta<<<PREP_BLOCKS + META_BLOCKS, 512>>>(x);
    irad_main<<<dim3(NTX, NTY, NB), 256>>>(out);
}

// round 16
// speedup vs baseline: 1.1851x; 1.1851x over previous
#include <cuda_runtime.h>
#include <math.h>

// Problem shapes (fixed): x (4,1,512,180) float32 -> out (4,1,512,512) float32
#define NB   4
#define H    512
#define WIN  180
#define L    180
#define W    512

// Padded pair table: index k = (b+1) + PAD, zeros outside valid core.
// Entries pre-rescaled: (P[b] - b*dP, dP) so sample = q.x + iy*q.y (iy global).
#define PAD      112
#define PSTRIDE2 744

__device__ static __align__(16) float2 g_pairs[NB * L * PSTRIDE2];

// Per-(tile, angle) metadata: (ca, -sa, as_float(ws), as_float(cnt16))
#define TJ   32
#define TI   32
#define NTX  (W / TJ)      // 16
#define NTY  (W / TI)      // 16
#define NMETA (NTX * NTY * L)
__device__ static float4 g_tmeta[NMETA];

// ---------------------------------------------------------------------------
// Fused prep + meta.
// ---------------------------------------------------------------------------
#define PREP_BLOCKS (NB * L)
#define META_BLOCKS ((NMETA + 511) / 512)

__global__ void __launch_bounds__(512) irad_prep_meta(const float* __restrict__ x) {
    __shared__ float col[H];
    const int bx  = blockIdx.x;
    const int tid = threadIdx.x;

    if (bx < PREP_BLOCKS) {
        const int l = bx % L;
        const int n = bx / L;

        float Xc  = fmaf((float)l, 2.0f / 179.0f, -1.0f);
        float ix  = (Xc + 1.0f) * 0.5f * 179.0f;
        float i0f = floorf(ix);
        float wx1 = ix - i0f;
        float wx0 = 1.0f - wx1;
        int   i0  = (int)i0f;
        int   i1  = i0 + 1;
        bool  v0  = (i0 >= 0) && (i0 <= WIN - 1);
        bool  v1  = (i1 >= 0) && (i1 <= WIN - 1);

        const float* xn = x + (size_t)n * H * WIN;
        {
            const int r = tid;                       // 512 threads = H rows
            float a = v0 ? xn[r * WIN + i0] : 0.0f;
            float b = v1 ? xn[r * WIN + i1] : 0.0f;
            col[r] = wx0 * a + wx1 * b;
        }
        __syncthreads();

        float2* pr = g_pairs + (size_t)(n * L + l) * PSTRIDE2;
        for (int k = tid; k < PSTRIDE2; k += 512) {
            int kk = k - PAD;                                    // = b+1
            float P  = (kk >= 1 && kk <= 512) ? col[kk - 1] : 0.0f;
            float Pn = (kk >= 0 && kk <= 511) ? col[kk]     : 0.0f;
            float d  = Pn - P;
            pr[k] = make_float2(fmaf(-(float)(kk - 1), d, P), d);
        }
    } else {
        int idx = (bx - PREP_BLOCKS) * 512 + tid;
        if (idx >= NMETA) return;
        int l    = idx % L;
        int tile = idx / L;
        int j0   = (tile % NTX) * TJ;
        int i0t  = (tile / NTX) * TI;

        float rad = (float)l * (3.14159265358979323846f / 180.0f);
        float ca  = cosf(rad) * 255.5f;
        float sa  = sinf(rad) * 255.5f;

        float uj0 = fmaf((float)j0,           2.0f / 511.0f, -1.0f);
        float uj1 = fmaf((float)(j0 + TJ-1),  2.0f / 511.0f, -1.0f);
        float vi0 = fmaf((float)i0t,          2.0f / 511.0f, -1.0f);
        float vi1 = fmaf((float)(i0t + TI-1), 2.0f / 511.0f, -1.0f);

        float jlo = fminf(ca * uj0, ca * uj1);
        float jhi = fmaxf(ca * uj0, ca * uj1);
        float ilo = fminf(sa * vi0, sa * vi1);
        float ihi = fmaxf(sa * vi0, sa * vi1);
        float iymin = 255.5f + jlo - ihi;
        float iymax = 255.5f + jhi - ilo;

        int ws  = (int)floorf(iymin);
        ws &= ~1;                                   // even for 16B alignment
        int cnt = (int)floorf(iymax) + 3 - ws;      // <= 48 entries
        int cnt16 = (cnt + 1) >> 1;                 // <= 24 16B chunks

        g_tmeta[idx] = make_float4(ca, -sa,
                                   __int_as_float(ws), __int_as_float(cnt16));
    }
}

// ---------------------------------------------------------------------------
// Main: 32x32 tile, 256 threads, 4 px/thread. Double-buffered chunks staged
// with single predicated 16B cp.async per lane using precomputed meta.
// __launch_bounds__(256, 8): force 32 regs so 8 blocks/SM fit (64 warps).
// ---------------------------------------------------------------------------
#define CH   30     // angles per chunk (180 = 6*30); smem fits 8 blocks/SM
#define NCH  (L / CH)
#define WMAX 48     // entries per angle window (384 B, 16B-aligned)

__device__ __forceinline__ void cp_async16(unsigned dst, const void* src) {
    asm volatile("cp.async.cg.shared.global [%0], [%1], 16;\n"
                 :: "r"(dst), "l"(src));
}
__device__ __forceinline__ void cp_async_commit() {
    asm volatile("cp.async.commit_group;\n");
}
__device__ __forceinline__ void cp_async_wait_all() {
    asm volatile("cp.async.wait_group 0;\n");
}

__global__ void __launch_bounds__(256, 8) irad_main(float* __restrict__ out) {
    __shared__ float2 sP[2 * CH * WMAX];
    __shared__ float4 sMeta[2 * CH];   // (ca, -sa, as_float(byte base), 0)

    const int n    = blockIdx.z;
    const int j0   = blockIdx.x * TJ;
    const int i0t  = blockIdx.y * TI;
    const int t    = threadIdx.x;
    const int lane = t & 31;
    const int wid  = t >> 5;           // 0..7
    const int j    = j0 + lane;

    const float uj = fmaf((float)j, 2.0f / 511.0f, -1.0f);

    float ui[4], acc[4];
#pragma unroll
    for (int k = 0; k < 4; k++) {
        ui[k]  = fmaf((float)(i0t + wid + 8 * k), 2.0f / 511.0f, -1.0f);
        acc[k] = 0.0f;
    }

    const float2* gp = g_pairs + (size_t)n * L * PSTRIDE2;
    const float4* tm = g_tmeta + (size_t)(blockIdx.y * NTX + blockIdx.x) * L;
    const char* sPc = (const char*)sP;
    const unsigned sPb = (unsigned)__cvta_generic_to_shared(sP);

    // ---- stage(chunk c into buffer b): LDG.128 meta + 1 cp.async/lane ----
    auto stage = [&](int c, int b) {
        const int c0 = c * CH;
        const int bofs = b * CH;
        for (int lc = wid; lc < CH; lc += 8) {
            const float4 m = tm[c0 + lc];
            const int ws    = __float_as_int(m.z);
            const int cnt16 = __float_as_int(m.w);

            const float2* src = gp + (size_t)(c0 + lc) * PSTRIDE2 + (ws + PAD);
            unsigned dst = sPb + (unsigned)((bofs + lc) * WMAX) * 8u;
            if (lane < cnt16)
                cp_async16(dst + (unsigned)lane * 16u, src + 2 * lane);
            if (lane == 0) {
                int ab8 = (((bofs + lc) * WMAX) + 1 - ws) * 8;
                sMeta[bofs + lc] = make_float4(m.x, m.y, __int_as_float(ab8), 0.0f);
            }
        }
        cp_async_commit();
    };

    stage(0, 0);

    for (int c = 0; c < NCH; c++) {
        const int b = c & 1;
        cp_async_wait_all();
        __syncthreads();                       // buf b ready; buf b^1 free

        if (c + 1 < NCH) stage(c + 1, b ^ 1);  // issue-only prefetch

        const float4* mp = sMeta + b * CH;
        for (int lc = 0; lc < CH; lc++) {
            const float4 m  = mp[lc];
            const char* pb  = sPc + __float_as_int(m.z);
            const float t0  = fmaf(m.x, uj, 255.5f);
#pragma unroll
            for (int k = 0; k < 4; k++) {
                float iy = fmaf(m.y, ui[k], t0);
                int   e  = __float2int_rd(iy);
                float2 q = *(const float2*)(pb + ((unsigned)e << 3));
                acc[k] = fmaf(iy, q.y, acc[k] + q.x);
            }
        }
    }

    const float scale = (float)(M_PI / 360.0);   // pi / (2*L)
    float* po = out + ((size_t)(n * W + i0t + wid) * W) + j;
#pragma unroll
    for (int k = 0; k < 4; k++) {
        po[(size_t)(8 * k) * W] = acc[k] * scale;
    }
}

// ---------------------------------------------------------------------------
extern "C" void kernel_launch(void* const* d_in, const int* in_sizes, int n_in,
                              void* d_out, int out_size) {
    const float* x = (const float*)d_in[0];
    float* out = (float*)d_out;
    (void)in_sizes; (void)n_in; (void)out_size;

    irad_prep_meta<<<PREP_BLOCKS + META_BLOCKS, 512>>>(x);
    irad_main<<<dim3(NTX, NTY, NB), 256>>>(out);
}

// round 17
// speedup vs baseline: 1.1949x; 1.0082x over previous
#include <cuda_runtime.h>
#include <math.h>

// Problem shapes (fixed): x (4,1,512,180) float32 -> out (4,1,512,512) float32
#define NB   4
#define H    512
#define WIN  180
#define L    180
#define W    512

// Padded pair table: index k = (b+1) + PAD, zeros outside valid core.
// Entries rescaled for SHIFTED coord iy128 = iy + 128:
//   value = q.x + iy128 * q.y  with  q.x = P - (b+128)*dP, q.y = dP
#define PAD      112
#define PSTRIDE2 744

__device__ static __align__(16) float2 g_pairs[NB * L * PSTRIDE2];

// Per-(tile, angle) metadata: (ca, -sa, as_float(ws), as_float(cnt16))
#define TJ   32
#define TI   32
#define NTX  (W / TJ)      // 16
#define NTY  (W / TI)      // 16
#define NMETA (NTX * NTY * L)
__device__ static float4 g_tmeta[NMETA];

#define MAGIC    8388608.0f          // 2^23
#define EXPFOLD  0x58000000u         // (0x4B000000 << 3) mod 2^32

// ---------------------------------------------------------------------------
// Fused prep + meta.
// ---------------------------------------------------------------------------
#define PREP_BLOCKS (NB * L)
#define META_BLOCKS ((NMETA + 511) / 512)

__global__ void __launch_bounds__(512) irad_prep_meta(const float* __restrict__ x) {
    __shared__ float col[H];
    const int bx  = blockIdx.x;
    const int tid = threadIdx.x;

    if (bx < PREP_BLOCKS) {
        const int l = bx % L;
        const int n = bx / L;

        float Xc  = fmaf((float)l, 2.0f / 179.0f, -1.0f);
        float ix  = (Xc + 1.0f) * 0.5f * 179.0f;
        float i0f = floorf(ix);
        float wx1 = ix - i0f;
        float wx0 = 1.0f - wx1;
        int   i0  = (int)i0f;
        int   i1  = i0 + 1;
        bool  v0  = (i0 >= 0) && (i0 <= WIN - 1);
        bool  v1  = (i1 >= 0) && (i1 <= WIN - 1);

        const float* xn = x + (size_t)n * H * WIN;
        {
            const int r = tid;                       // 512 threads = H rows
            float a = v0 ? xn[r * WIN + i0] : 0.0f;
            float b = v1 ? xn[r * WIN + i1] : 0.0f;
            col[r] = wx0 * a + wx1 * b;
        }
        __syncthreads();

        float2* pr = g_pairs + (size_t)(n * L + l) * PSTRIDE2;
        for (int k = tid; k < PSTRIDE2; k += 512) {
            int kk = k - PAD;                                    // = b+1
            float P  = (kk >= 1 && kk <= 512) ? col[kk - 1] : 0.0f;
            float Pn = (kk >= 0 && kk <= 511) ? col[kk]     : 0.0f;
            float d  = Pn - P;
            // shifted rescale: value = q.x + (iy+128)*d for floor(iy) = kk-1
            pr[k] = make_float2(fmaf(-(float)(kk - 1 + 128), d, P), d);
        }
    } else {
        int idx = (bx - PREP_BLOCKS) * 512 + tid;
        if (idx >= NMETA) return;
        int l    = idx % L;
        int tile = idx / L;
        int j0   = (tile % NTX) * TJ;
        int i0t  = (tile / NTX) * TI;

        float rad = (float)l * (3.14159265358979323846f / 180.0f);
        float ca  = cosf(rad) * 255.5f;
        float sa  = sinf(rad) * 255.5f;

        float uj0 = fmaf((float)j0,           2.0f / 511.0f, -1.0f);
        float uj1 = fmaf((float)(j0 + TJ-1),  2.0f / 511.0f, -1.0f);
        float vi0 = fmaf((float)i0t,          2.0f / 511.0f, -1.0f);
        float vi1 = fmaf((float)(i0t + TI-1), 2.0f / 511.0f, -1.0f);

        float jlo = fminf(ca * uj0, ca * uj1);
        float jhi = fmaxf(ca * uj0, ca * uj1);
        float ilo = fminf(sa * vi0, sa * vi1);
        float ihi = fmaxf(sa * vi0, sa * vi1);
        float iymin = 255.5f + jlo - ihi;
        float iymax = 255.5f + jhi - ilo;

        int ws  = (int)floorf(iymin);
        ws &= ~1;                                   // even for 16B alignment
        int cnt = (int)floorf(iymax) + 3 - ws;      // <= 48 entries
        int cnt16 = (cnt + 1) >> 1;                 // <= 24 16B chunks

        g_tmeta[idx] = make_float4(ca, -sa,
                                   __int_as_float(ws), __int_as_float(cnt16));
    }
}

// ---------------------------------------------------------------------------
// Main: 32x32 tile, 256 threads, 4 px/thread, 8 blocks/SM forced.
// floor() via round-down magic add; exponent+base folded into per-angle mz.
// ---------------------------------------------------------------------------
#define CH   30     // angles per chunk (180 = 6*30); smem fits 8 blocks/SM
#define NCH  (L / CH)
#define WMAX 48     // entries per angle window (384 B, 16B-aligned)

__device__ __forceinline__ void cp_async16(unsigned dst, const void* src) {
    asm volatile("cp.async.cg.shared.global [%0], [%1], 16;\n"
                 :: "r"(dst), "l"(src));
}
__device__ __forceinline__ void cp_async_commit() {
    asm volatile("cp.async.commit_group;\n");
}
__device__ __forceinline__ void cp_async_wait_all() {
    asm volatile("cp.async.wait_group 0;\n");
}

__global__ void __launch_bounds__(256, 8) irad_main(float* __restrict__ out) {
    __shared__ float2 sP[2 * CH * WMAX];
    __shared__ float4 sMeta[2 * CH];   // (ca, -sa, as_float(mz), 0)

    const int n    = blockIdx.z;
    const int j0   = blockIdx.x * TJ;
    const int i0t  = blockIdx.y * TI;
    const int t    = threadIdx.x;
    const int lane = t & 31;
    const int wid  = t >> 5;           // 0..7
    const int j    = j0 + lane;

    const float uj = fmaf((float)j, 2.0f / 511.0f, -1.0f);

    float ui[4], acc[4];
#pragma unroll
    for (int k = 0; k < 4; k++) {
        ui[k]  = fmaf((float)(i0t + wid + 8 * k), 2.0f / 511.0f, -1.0f);
        acc[k] = 0.0f;
    }

    const float2* gp = g_pairs + (size_t)n * L * PSTRIDE2;
    const float4* tm = g_tmeta + (size_t)(blockIdx.y * NTX + blockIdx.x) * L;
    const char* sPc = (const char*)sP;
    const unsigned sPb = (unsigned)__cvta_generic_to_shared(sP);

    // ---- stage(chunk c into buffer b): LDG.128 meta + 1 cp.async/lane ----
    auto stage = [&](int c, int b) {
        const int c0 = c * CH;
        const int bofs = b * CH;
        for (int lc = wid; lc < CH; lc += 8) {
            const float4 m = tm[c0 + lc];
            const int ws    = __float_as_int(m.z);
            const int cnt16 = __float_as_int(m.w);

            const float2* src = gp + (size_t)(c0 + lc) * PSTRIDE2 + (ws + PAD);
            unsigned dst = sPb + (unsigned)((bofs + lc) * WMAX) * 8u;
            if (lane < cnt16)
                cp_async16(dst + (unsigned)lane * 16u, src + 2 * lane);
            if (lane == 0) {
                // slot for floor e is (e - ws + 1); f-bits = 0x4B000000 + e + 128
                // off = (bits(f)<<3) + mz  ==  ((bofs+lc)*WMAX + e - ws + 1)*8
                unsigned mz = (unsigned)(((bofs + lc) * WMAX + 1 - ws - 128) * 8)
                              - EXPFOLD;
                sMeta[bofs + lc] = make_float4(m.x, m.y, __uint_as_float(mz), 0.0f);
            }
        }
        cp_async_commit();
    };

    stage(0, 0);

    for (int c = 0; c < NCH; c++) {
        const int b = c & 1;
        cp_async_wait_all();
        __syncthreads();                       // buf b ready; buf b^1 free

        if (c + 1 < NCH) stage(c + 1, b ^ 1);  // issue-only prefetch

        const float4* mp = sMeta + b * CH;
        for (int lc = 0; lc < CH; lc++) {
            const float4 m    = mp[lc];
            const unsigned mz = __float_as_uint(m.z);
            const float t0    = fmaf(m.x, uj, 383.5f);   // 255.5 + 128
#pragma unroll
            for (int k = 0; k < 4; k++) {
                float iy = fmaf(m.y, ui[k], t0);               // shifted coord
                float f  = __fadd_rd(iy, MAGIC);               // 2^23 + floor
                unsigned off = (__float_as_uint(f) << 3) + mz; // byte offset
                float2 q = *(const float2*)(sPc + off);
                acc[k] = fmaf(iy, q.y, acc[k] + q.x);
            }
        }
    }

    const float scale = (float)(M_PI / 360.0);   // pi / (2*L)
    float* po = out + ((size_t)(n * W + i0t + wid) * W) + j;
#pragma unroll
    for (int k = 0; k < 4; k++) {
        po[(size_t)(8 * k) * W] = acc[k] * scale;
    }
}

// ---------------------------------------------------------------------------
extern "C" void kernel_launch(void* const* d_in, const int* in_sizes, int n_in,
                              void* d_out, int out_size) {
    const float* x = (const float*)d_in[0];
    float* out = (float*)d_out;
    (void)in_sizes; (void)n_in; (void)out_size;

    irad_prep_meta<<<PREP_BLOCKS + META_BLOCKS, 512>>>(x);
    irad_main<<<dim3(NTX, NTY, NB), 256>>>(out);
}